// round 17
// baseline (speedup 1.0000x reference)
#include <cuda_runtime.h>
#include <cuda_fp16.h>
#include <cstdint>

#define NUNITS 4096
#define NCTAS  296
#define GST    262144              // halfs per (f,g) slab; layout [f][g][i][o]

__device__ __half g_fcH[26214400];  // fc * 256 in fp16, same index order as fc

__device__ __forceinline__ void cpa16(uint32_t s, const void* g){
    asm volatile("cp.async.cg.shared.global [%0], [%1], 16;" :: "r"(s), "l"(g));
}
__device__ __forceinline__ uint32_t ph2(float lo, float hi){
    __half2 h = __floats2half2_rn(lo, hi);
    return *reinterpret_cast<uint32_t*>(&h);
}
__device__ __forceinline__ void mma16(float* d, const uint4 a, uint32_t b0, uint32_t b1){
    asm volatile("mma.sync.aligned.m16n8k16.row.col.f32.f16.f16.f32 "
        "{%0,%1,%2,%3}, {%4,%5,%6,%7}, {%8,%9}, {%0,%1,%2,%3};"
        : "+f"(d[0]),"+f"(d[1]),"+f"(d[2]),"+f"(d[3])
        : "r"(a.x),"r"(a.y),"r"(a.z),"r"(a.w), "r"(b0),"r"(b1));
}

// pure streaming convert: g_fcH = fp16(fc * 256); fold out = bias init.
__global__ void __launch_bounds__(256) prep_kernel(const float* __restrict__ fc,
                                                   const float* __restrict__ bias,
                                                   float* __restrict__ out){
    size_t idx = ((size_t)blockIdx.x*256 + threadIdx.x)*8;
    float4 v0 = *(const float4*)(fc + idx);
    float4 v1 = *(const float4*)(fc + idx + 4);
    uint4 h = make_uint4(ph2(v0.x*256.f, v0.y*256.f), ph2(v0.z*256.f, v0.w*256.f),
                         ph2(v1.x*256.f, v1.y*256.f), ph2(v1.z*256.f, v1.w*256.f));
    *(uint4*)(g_fcH + idx) = h;
    if (blockIdx.x < 1024){
        int o = blockIdx.x*1024 + threadIdx.x*4;
        *(float4*)(out + o) = *(const float4*)(bias + (o & 511));
    }
}

__global__ void __launch_bounds__(128,2)
fkan_fp16(const float* __restrict__ x, float* __restrict__ out)
{
    __shared__ __align__(16) char Bh[2][4608];   // [buf][k=32 rows x 144B pitch]

    const int tid  = threadIdx.x;
    const int lane = tid & 31;
    const int wm   = tid >> 5;            // warp = 32m x 64n
    const int gid  = lane >> 2, tig = lane & 3, l7 = lane & 7;

    const uint32_t bh_sa = (uint32_t)__cvta_generic_to_shared(&Bh[0][0]);

    // cp.async map: 256 chunks/buffer, 2 per thread. chunk: row ck (k), n-octet j.
    uint32_t cdst[2]; const __half* cbase[2];
#pragma unroll
    for (int q=0;q<2;++q){
        int cidx = q*128 + tid, ck = cidx>>3, j = cidx&7;
        int f = ck>>4, il = ck&15;
        cdst[q]  = bh_sa + (uint32_t)(ck*144 + ((j ^ (ck&7))<<4));
        cbase[q] = g_fcH + ((size_t)(f*50)*512 + il)*512 + 8*j;
    }

    // ldmatrix row base (x2: lanes 0-15 give addresses for 16 k-rows)
    const uint32_t lmrow = (uint32_t)((((lane>>3)&1)*8 + l7) * 144);

    const int c = blockIdx.x;
    const int u0 = (NUNITS*c)/NCTAS, u1 = (NUNITS*(c+1))/NCTAS;

    float acc[2][8][4];
#pragma unroll
    for (int a1=0;a1<2;++a1)
#pragma unroll
    for (int b1=0;b1<8;++b1)
#pragma unroll
    for (int d1=0;d1<4;++d1) acc[a1][b1][d1]=0.f;

    int cur_tile = -1, cm0 = 0, cn0 = 0;
    const float SC = 1.f/256.f;

    for (int u = u0; u < u1; ++u){
        const int tile = u >> 5, ic = u & 31;
        const int m0 = (tile>>3)*128, n0 = (tile&7)*64, ib = ic*16;

        if (tile != cur_tile){
            if (cur_tile >= 0){
#pragma unroll
                for (int mt=0;mt<2;++mt)
#pragma unroll
                for (int nt=0;nt<8;++nt){
                    float* op = out + (size_t)(cm0 + wm*32 + mt*16 + gid)*512 + cn0 + nt*8 + 2*tig;
                    atomicAdd(op,      acc[mt][nt][0]*SC);
                    atomicAdd(op+1,    acc[mt][nt][1]*SC);
                    atomicAdd(op+4096, acc[mt][nt][2]*SC);
                    atomicAdd(op+4097, acc[mt][nt][3]*SC);
                }
#pragma unroll
                for (int a1=0;a1<2;++a1)
#pragma unroll
                for (int b1=0;b1<8;++b1)
#pragma unroll
                for (int d1=0;d1<4;++d1) acc[a1][b1][d1]=0.f;
            }
            cur_tile = tile; cm0 = m0; cn0 = n0;
        }

        // ---- init rotation states (k=1) in mma-fragment layout ----
        // j = mt*8 + mh*4 + iv : m = m0+wm*32+mt*16+gid+8*mh, i = ib+2*tig+(iv&1)+8*(iv>>1)
        float ss[16], cc[16], s1[16], c1[16];
#pragma unroll
        for (int mt=0; mt<2; ++mt)
#pragma unroll
        for (int mh=0; mh<2; ++mh)
#pragma unroll
        for (int iv=0; iv<4; ++iv){
            int j = mt*8 + mh*4 + iv;
            int i = ib + 2*tig + (iv&1) + 8*(iv>>1);
            int m = m0 + wm*32 + mt*16 + gid + 8*mh;
            float xv = __ldg(x + (size_t)m*512 + i);
            sincospif(xv, &s1[j], &c1[j]);
            ss[j]=s1[j]; cc[j]=c1[j];
        }

        const size_t uoff = (size_t)ib*512 + n0;

        // ---- prologue: B(g=0) into buf 0 ----
        cpa16(cdst[0], cbase[0] + uoff);
        cpa16(cdst[1], cbase[1] + uoff);
        asm volatile("cp.async.commit_group;");

#pragma unroll 2
        for (int g=0; g<50; ++g){
            const int cur = g&1, nxt = cur^1;
            const bool hn = (g < 49);

            // pack A fragments for this g (registers only)
            uint4 a[2][2];
#pragma unroll
            for (int mt=0; mt<2; ++mt){
                int b = mt*8;
                a[mt][0] = make_uint4(ph2(ss[b+0],ss[b+1]), ph2(ss[b+4],ss[b+5]),
                                      ph2(ss[b+2],ss[b+3]), ph2(ss[b+6],ss[b+7]));
                a[mt][1] = make_uint4(ph2(cc[b+0],cc[b+1]), ph2(cc[b+4],cc[b+5]),
                                      ph2(cc[b+2],cc[b+3]), ph2(cc[b+6],cc[b+7]));
            }
            if (hn){
#pragma unroll
                for (int j=0;j<16;++j){
                    float ns = fmaf(ss[j], c1[j],  cc[j]*s1[j]);
                    float nc = fmaf(cc[j], c1[j], -ss[j]*s1[j]);
                    ss[j]=ns; cc[j]=nc;
                }
            }

            asm volatile("cp.async.wait_group 0;");
            __syncthreads();      // B[cur] visible to all; B[nxt] safe to overwrite

            if (hn){
                size_t go = uoff + (size_t)(g+1)*GST;
                cpa16(cdst[0] + nxt*4608u, cbase[0] + go);
                cpa16(cdst[1] + nxt*4608u, cbase[1] + go);
                asm volatile("cp.async.commit_group;");
            }

            // ---- GEMM: 128m x 64n x 32k; warp = 32m x 64n ----
            const uint32_t bb = bh_sa + (uint32_t)cur*4608u + lmrow;
#pragma unroll
            for (int kt=0; kt<2; ++kt){
#pragma unroll
                for (int nt=0; nt<8; ++nt){
                    uint32_t ad = bb + (uint32_t)kt*2304u + ((uint32_t)(nt ^ l7) << 4);
                    uint32_t b0, b1;
                    asm volatile("ldmatrix.sync.aligned.m8n8.x2.trans.shared.b16 {%0,%1}, [%2];"
                                 : "=r"(b0), "=r"(b1) : "r"(ad));
                    mma16(acc[0][nt], a[0][kt], b0, b1);
                    mma16(acc[1][nt], a[1][kt], b0, b1);
                }
            }
        }
    }

    // final flush
    if (cur_tile >= 0){
#pragma unroll
        for (int mt=0;mt<2;++mt)
#pragma unroll
        for (int nt=0;nt<8;++nt){
            float* op = out + (size_t)(cm0 + wm*32 + mt*16 + gid)*512 + cn0 + nt*8 + 2*tig;
            atomicAdd(op,      acc[mt][nt][0]*SC);
            atomicAdd(op+1,    acc[mt][nt][1]*SC);
            atomicAdd(op+4096, acc[mt][nt][2]*SC);
            atomicAdd(op+4097, acc[mt][nt][3]*SC);
        }
    }
}

extern "C" void kernel_launch(void* const* d_in, const int* in_sizes, int n_in,
                              void* d_out, int out_size) {
    const float* x    = (const float*)d_in[0];
    const float* fc   = (const float*)d_in[1];
    const float* bias = (const float*)d_in[2];
    float* out = (float*)d_out;

    prep_kernel<<<12800, 256>>>(fc, bias, out);
    fkan_fp16<<<NCTAS, 128>>>(x, out);
}